// round 1
// baseline (speedup 1.0000x reference)
#include <cuda_runtime.h>
#include <cstdint>

// MixtureLowRankRNN — GB300 sm_103a
//
// Output identity: h_t lies exactly in colspan([m | I_mat]) since h0 = 0, so
// pinv(span) @ h_t recovers the basis coordinates directly:
//   y[b,t,0:4]  = alpha*scale * S_{t+1},  S <- 0.9 S + u_t,  u_t = n^T tanh(h_t)
//   y[b,t,4:20] = alpha * X_{t+1},        X <- 0.9 X + x_t
// So we only run the recurrence (u_t needs tanh(h) over H=1024) and two tiny
// decayed cumulative sums. No hiddens buffer, no pinv, no projection GEMM.

#define HID   1024
#define RANKN 4
#define INPN  16
#define TLEN  1024
#define BATCH 32
#define NTHR  256   // 4 elements per thread

typedef unsigned long long u64;

__device__ __forceinline__ u64 pack2(float x, float y) {
    u64 r; asm("mov.b64 %0, {%1, %2};" : "=l"(r) : "f"(x), "f"(y)); return r;
}
__device__ __forceinline__ void unpack2(u64 v, float& x, float& y) {
    asm("mov.b64 {%0, %1}, %2;" : "=f"(x), "=f"(y) : "l"(v));
}
__device__ __forceinline__ u64 fma2(u64 a, u64 b, u64 c) {
    u64 d; asm("fma.rn.f32x2 %0, %1, %2, %3;" : "=l"(d) : "l"(a), "l"(b), "l"(c)); return d;
}
__device__ __forceinline__ u64 mul2(u64 a, u64 b) {
    u64 d; asm("mul.rn.f32x2 %0, %1, %2;" : "=l"(d) : "l"(a), "l"(b)); return d;
}

// Accurate branch-free tanh: 1 - 2/(1 + e^{2x}) via ex2.approx + rcp.approx.
// ex2/rcp approx errors are ~2^-22 -> tanh error ~1e-6 (vs ~5e-4 for tanh.approx).
// Saturation handled naturally: e -> 0 gives -1, e -> inf gives +1.
__device__ __forceinline__ float fast_tanh(float x) {
    float e, r;
    asm("ex2.approx.f32 %0, %1;" : "=f"(e) : "f"(x * 2.885390081777927f)); // 2*log2(e)
    asm("rcp.approx.f32 %0, %1;" : "=f"(r) : "f"(e + 1.0f));
    return fmaf(-2.0f, r, 1.0f);
}

__global__ __launch_bounds__(NTHR, 1)
void rnn_kernel(const float* __restrict__ x,   // [B, T, 16]
                const float* __restrict__ m,   // [H, 4]
                const float* __restrict__ n,   // [H, 4]
                const float* __restrict__ I,   // [H, 16]
                float* __restrict__ out)       // [B, T, 20]
{
    const int b    = blockIdx.x;
    const int tid  = threadIdx.x;
    const int wid  = tid >> 5;
    const int lane = tid & 31;

    __shared__ float4 s_part[8];      // per-warp partial u
    __shared__ u64    s_ud[4];        // u_t, each value duplicated in both halves
    __shared__ u64    s_xd[2][16];    // raw x_t duplicated, double buffered

    // ---- preload weights into registers, prefold scale factors ----
    const float a_s = 0.1f * (500.0f / 1024.0f);  // alpha*scale
    const int eA0 = tid,        eA1 = tid + 256;
    const int eB0 = tid + 512,  eB1 = tid + 768;

    u64 ma[RANKN], mb[RANKN], na[RANKN], nb[RANKN], Ia[INPN], Ib[INPN];
#pragma unroll
    for (int r = 0; r < RANKN; r++) {
        ma[r] = pack2(a_s * m[eA0 * RANKN + r], a_s * m[eA1 * RANKN + r]);
        mb[r] = pack2(a_s * m[eB0 * RANKN + r], a_s * m[eB1 * RANKN + r]);
        na[r] = pack2(n[eA0 * RANKN + r], n[eA1 * RANKN + r]);
        nb[r] = pack2(n[eB0 * RANKN + r], n[eB1 * RANKN + r]);
    }
#pragma unroll
    for (int j = 0; j < INPN; j++) {
        Ia[j] = pack2(0.1f * I[eA0 * INPN + j], 0.1f * I[eA1 * INPN + j]);
        Ib[j] = pack2(0.1f * I[eB0 * INPN + j], 0.1f * I[eB1 * INPN + j]);
    }

    u64 hA = 0ull, hB = 0ull;             // h = 0 (two packed zeros each)
    const u64 c9 = pack2(0.9f, 0.9f);     // 1 - alpha

    const float* xb   = x   + (size_t)b * TLEN * INPN;
    float*       outb = out + (size_t)b * TLEN * 20;

    // warp-role state
    float4 S = make_float4(0.f, 0.f, 0.f, 0.f);  // warp0 lane0
    float  X = 0.f;                              // warp1 lanes 0..15
    float  xcur = 0.f;

    // prologue: stage x_0
    if (wid == 1 && lane < INPN) {
        xcur = xb[lane];
        s_xd[0][lane] = pack2(xcur, xcur);
    }
    __syncthreads();

    for (int t = 0; t < TLEN; t++) {
        // ---- phase 1: tanh(h_t) and partial u ----
        float a0, a1, b0, b1;
        unpack2(hA, a0, a1); unpack2(hB, b0, b1);
        u64 thA = pack2(fast_tanh(a0), fast_tanh(a1));
        u64 thB = pack2(fast_tanh(b0), fast_tanh(b1));

        float p[4];
#pragma unroll
        for (int r = 0; r < RANKN; r++) {
            u64 pr = fma2(na[r], thA, mul2(nb[r], thB));
            float lo, hi; unpack2(pr, lo, hi);
            p[r] = lo + hi;
        }
#pragma unroll
        for (int off = 16; off > 0; off >>= 1) {
            p[0] += __shfl_xor_sync(0xffffffffu, p[0], off);
            p[1] += __shfl_xor_sync(0xffffffffu, p[1], off);
            p[2] += __shfl_xor_sync(0xffffffffu, p[2], off);
            p[3] += __shfl_xor_sync(0xffffffffu, p[3], off);
        }
        if (lane == 0) s_part[wid] = make_float4(p[0], p[1], p[2], p[3]);
        __syncthreads();   // bar1

        // ---- phase 2a (all warps): u-independent part of h update ----
        const int buf = t & 1;
        u64 accA = mul2(hA, c9);
        u64 accB = mul2(hB, c9);
#pragma unroll
        for (int j = 0; j < INPN; j++) {
            u64 xj = s_xd[buf][j];
            accA = fma2(Ia[j], xj, accA);
            accB = fma2(Ib[j], xj, accB);
        }

        // ---- phase 2b (warp0): final u reduce + low-rank output ----
        if (wid == 0) {
            float4 q = s_part[lane & 7];
#pragma unroll
            for (int off = 4; off > 0; off >>= 1) {
                q.x += __shfl_xor_sync(0xffffffffu, q.x, off);
                q.y += __shfl_xor_sync(0xffffffffu, q.y, off);
                q.z += __shfl_xor_sync(0xffffffffu, q.z, off);
                q.w += __shfl_xor_sync(0xffffffffu, q.w, off);
            }
            if (lane == 0) {
                s_ud[0] = pack2(q.x, q.x);
                s_ud[1] = pack2(q.y, q.y);
                s_ud[2] = pack2(q.z, q.z);
                s_ud[3] = pack2(q.w, q.w);
                S.x = fmaf(0.9f, S.x, q.x);
                S.y = fmaf(0.9f, S.y, q.y);
                S.z = fmaf(0.9f, S.z, q.z);
                S.w = fmaf(0.9f, S.w, q.w);
                *(float4*)(outb + (size_t)t * 20) =
                    make_float4(a_s * S.x, a_s * S.y, a_s * S.z, a_s * S.w);
            }
        }
        // ---- phase 2c (warp1): input-coordinate output + stage x_{t+1} ----
        else if (wid == 1 && lane < INPN) {
            X = fmaf(0.9f, X, xcur);
            outb[(size_t)t * 20 + 4 + lane] = 0.1f * X;
            if (t + 1 < TLEN) {
                xcur = xb[(size_t)(t + 1) * INPN + lane];
                s_xd[(t + 1) & 1][lane] = pack2(xcur, xcur);
            }
        }
        __syncthreads();   // bar2

        // ---- phase 3: add recurrent term ----
#pragma unroll
        for (int r = 0; r < RANKN; r++) {
            u64 ur = s_ud[r];
            accA = fma2(ma[r], ur, accA);
            accB = fma2(mb[r], ur, accB);
        }
        hA = accA;
        hB = accB;
    }
}

extern "C" void kernel_launch(void* const* d_in, const int* in_sizes, int n_in,
                              void* d_out, int out_size) {
    const float* x = (const float*)d_in[0];
    const float* m = (const float*)d_in[1];
    const float* n = (const float*)d_in[2];
    const float* I = (const float*)d_in[3];
    rnn_kernel<<<BATCH, NTHR>>>(x, m, n, I, (float*)d_out);
}

// round 2
// speedup vs baseline: 1.0431x; 1.0431x over previous
#include <cuda_runtime.h>
#include <cstdint>

// MixtureLowRankRNN — GB300 sm_103a. Subspace identity: h_t ∈ colspan([m|I]),
// so outputs are the basis coordinates:
//   y[:,t,0:4]  = a_s*S_{t+1},  S <- 0.9 S + u_t,  u_t = n^T tanh(h_t)
//   y[:,t,4:20] = 0.1*X_{t+1},  X <- 0.9 X + x_t
// tanh fold: u_r = Nsum_r - 2*R_r, R_r = sum_h n[h,r] * r_h, r_h = 1/(1+e^{2h}).
// The Nsum part folds into a per-element additive constant in the h update.

#define HID   1024
#define RANKN 4
#define INPN  16
#define TLEN  1024
#define BATCH 32
#define NTHR  256

typedef unsigned long long u64;

__device__ __forceinline__ u64 pack2(float x, float y) {
    u64 r; asm("mov.b64 %0, {%1, %2};" : "=l"(r) : "f"(x), "f"(y)); return r;
}
__device__ __forceinline__ void unpack2(u64 v, float& x, float& y) {
    asm("mov.b64 {%0, %1}, %2;" : "=f"(x), "=f"(y) : "l"(v));
}
__device__ __forceinline__ u64 fma2(u64 a, u64 b, u64 c) {
    u64 d; asm("fma.rn.f32x2 %0, %1, %2, %3;" : "=l"(d) : "l"(a), "l"(b), "l"(c)); return d;
}
__device__ __forceinline__ u64 mul2(u64 a, u64 b) {
    u64 d; asm("mul.rn.f32x2 %0, %1, %2;" : "=l"(d) : "l"(a), "l"(b)); return d;
}
__device__ __forceinline__ u64 add2(u64 a, u64 b) {
    u64 d; asm("add.rn.f32x2 %0, %1, %2;" : "=l"(d) : "l"(a), "l"(b)); return d;
}

// r(x) = 1/(1 + e^{2x}) = (1 - tanh x)/2, accurate to ~1e-6.
__device__ __forceinline__ float rcore(float x) {
    float e, r;
    asm("ex2.approx.f32 %0, %1;" : "=f"(e) : "f"(x * 2.885390081777927f)); // 2*log2(e)
    asm("rcp.approx.f32 %0, %1;" : "=f"(r) : "f"(e + 1.0f));
    return r;
}

// Reduce 4 values across a warp with 6 shfls: returns warp-sum of p_{lane&3}.
__device__ __forceinline__ float warp_reduce4(float p0, float p1, float p2, float p3, int lane) {
    const bool b0 = lane & 1;
    const bool b1 = lane & 2;
    float sA = b0 ? p0 : p1;
    float rA = __shfl_xor_sync(0xffffffffu, sA, 1);
    float q0 = (b0 ? p1 : p0) + rA;          // pair-sum of p_{b0}
    float sB = b0 ? p2 : p3;
    float rB = __shfl_xor_sync(0xffffffffu, sB, 1);
    float q1 = (b0 ? p3 : p2) + rB;          // pair-sum of p_{2+b0}
    float sC = b1 ? q0 : q1;
    float rC = __shfl_xor_sync(0xffffffffu, sC, 2);
    float w  = (b1 ? q1 : q0) + rC;          // 4-lane sum of p_{lane&3}
    w += __shfl_xor_sync(0xffffffffu, w, 4);
    w += __shfl_xor_sync(0xffffffffu, w, 8);
    w += __shfl_xor_sync(0xffffffffu, w, 16);
    return w;
}

__global__ __launch_bounds__(NTHR, 1)
void rnn_kernel(const float* __restrict__ x,   // [B, T, 16]
                const float* __restrict__ m,   // [H, 4]
                const float* __restrict__ n,   // [H, 4]
                const float* __restrict__ I,   // [H, 16]
                float* __restrict__ out)       // [B, T, 20]
{
    const int b    = blockIdx.x;
    const int tid  = threadIdx.x;
    const int wid  = tid >> 5;
    const int lane = tid & 31;

    __shared__ ulonglong2 s_part[2][8];   // per-warp {p0,p1},{p2,p3}, double buffered
    __shared__ u64        s_x[4][16];     // duplicated x_t, 4-deep rotation

    const float a_s = 0.1f * (500.0f / 1024.0f);
    const int eA0 = tid,        eA1 = tid + 256;
    const int eB0 = tid + 512,  eB1 = tid + 768;

    u64 na[RANKN], nb[RANKN], m2a[RANKN], m2b[RANKN], Ia[INPN], Ib[INPN];
    u64 msA[RANKN], msB[RANKN];
#pragma unroll
    for (int r = 0; r < RANKN; r++) {
        na[r]  = pack2(n[eA0 * RANKN + r], n[eA1 * RANKN + r]);
        nb[r]  = pack2(n[eB0 * RANKN + r], n[eB1 * RANKN + r]);
        msA[r] = pack2(a_s * m[eA0 * RANKN + r], a_s * m[eA1 * RANKN + r]);
        msB[r] = pack2(a_s * m[eB0 * RANKN + r], a_s * m[eB1 * RANKN + r]);
    }
#pragma unroll
    for (int j = 0; j < INPN; j++) {
        Ia[j] = pack2(0.1f * I[eA0 * INPN + j], 0.1f * I[eA1 * INPN + j]);
        Ib[j] = pack2(0.1f * I[eB0 * INPN + j], 0.1f * I[eB1 * INPN + j]);
    }

    const u64 c9   = pack2(0.9f, 0.9f);
    const u64 neg2 = pack2(-2.0f, -2.0f);
    const u64 asd  = pack2(a_s, a_s);

    const float* xb   = x   + (size_t)b * TLEN * INPN;
    float*       outb = out + (size_t)b * TLEN * 20;

    // warp-role state
    u64   S01 = 0ull, S23 = 0ull;   // warp0 lane0
    float X = 0.f, xv = 0.f, xn = 0.f, xf = 0.f;

    // ================= prologue: Nsum_r = sum_h n[h,r] =================
    {
        float l0, h0, l1, h1;
        float p[4];
#pragma unroll
        for (int r = 0; r < RANKN; r++) {
            u64 s = add2(na[r], nb[r]);
            unpack2(s, l0, h0);
            p[r] = l0 + h0;
        }
        float w = warp_reduce4(p[0], p[1], p[2], p[3], lane);
        if (lane < 4) ((float*)&s_part[1][wid])[lane] = w;
        if (wid == 1 && lane < INPN) {
            xv = xb[lane];
            xn = xb[INPN + lane];
            s_x[0][lane] = pack2(xv, xv);
        }
        (void)l1; (void)h1;
    }
    __syncthreads();

    u64 NS01, NS23;
    {
        ulonglong2 v[8];
#pragma unroll
        for (int i = 0; i < 8; i++) v[i] = s_part[1][i];
        NS01 = add2(add2(add2(v[0].x, v[1].x), add2(v[2].x, v[3].x)),
                    add2(add2(v[4].x, v[5].x), add2(v[6].x, v[7].x)));
        NS23 = add2(add2(add2(v[0].y, v[1].y), add2(v[2].y, v[3].y)),
                    add2(add2(v[4].y, v[5].y), add2(v[6].y, v[7].y)));
    }
    float ns0, ns1, ns2, ns3;
    unpack2(NS01, ns0, ns1); unpack2(NS23, ns2, ns3);
    const u64 N0d = pack2(ns0, ns0), N1d = pack2(ns1, ns1);
    const u64 N2d = pack2(ns2, ns2), N3d = pack2(ns3, ns3);

    // kA = sum_r (a_s*m_r)*Nsum_r  (per element pair), m2 = -2*a_s*m
    u64 kAa = fma2(msA[0], N0d, fma2(msA[1], N1d, fma2(msA[2], N2d, mul2(msA[3], N3d))));
    u64 kAb = fma2(msB[0], N0d, fma2(msB[1], N1d, fma2(msB[2], N2d, mul2(msB[3], N3d))));
#pragma unroll
    for (int r = 0; r < RANKN; r++) {
        m2a[r] = mul2(msA[r], neg2);
        m2b[r] = mul2(msB[r], neg2);
    }

    u64 hA = 0ull, hB = 0ull;

    // ================= main recurrence =================
    for (int t = 0; t < TLEN; t++) {
        // ---- r-core + low-rank dot (R_r = sum n*r) ----
        float a0, a1, b0v, b1v;
        unpack2(hA, a0, a1); unpack2(hB, b0v, b1v);
        u64 rA = pack2(rcore(a0), rcore(a1));
        u64 rB = pack2(rcore(b0v), rcore(b1v));

        float p[4];
#pragma unroll
        for (int r = 0; r < RANKN; r++) {
            u64 pr = fma2(na[r], rA, mul2(nb[r], rB));
            float lo, hi; unpack2(pr, lo, hi);
            p[r] = lo + hi;
        }

        // ---- u-independent part of update (overlaps reduce latency) ----
        u64 accA = fma2(c9, hA, kAa);
        u64 accB = fma2(c9, hB, kAb);
#pragma unroll
        for (int j = 0; j < INPN; j++) {
            u64 xj = s_x[t & 3][j];
            accA = fma2(Ia[j], xj, accA);
            accB = fma2(Ib[j], xj, accB);
        }

        // ---- per-warp reduce, publish ----
        float w = warp_reduce4(p[0], p[1], p[2], p[3], lane);
        if (lane < 4) ((float*)&s_part[t & 1][wid])[lane] = w;

        // ---- stage x_{t+1}, prefetch x_{t+2} ----
        if (wid == 1 && lane < INPN) {
            s_x[(t + 1) & 3][lane] = pack2(xn, xn);
            xf = (t + 2 < TLEN) ? xb[(size_t)(t + 2) * INPN + lane] : 0.f;
        }

        __syncthreads();   // the only barrier per step

        // ---- redundant cross-warp sum (broadcast LDS, everyone gets R) ----
        ulonglong2 v[8];
#pragma unroll
        for (int i = 0; i < 8; i++) v[i] = s_part[t & 1][i];
        u64 R01 = add2(add2(add2(v[0].x, v[1].x), add2(v[2].x, v[3].x)),
                       add2(add2(v[4].x, v[5].x), add2(v[6].x, v[7].x)));
        u64 R23 = add2(add2(add2(v[0].y, v[1].y), add2(v[2].y, v[3].y)),
                       add2(add2(v[4].y, v[5].y), add2(v[6].y, v[7].y)));

        float U0, U1, U2, U3;
        unpack2(R01, U0, U1); unpack2(R23, U2, U3);
        u64 R0d = pack2(U0, U0), R1d = pack2(U1, U1);
        u64 R2d = pack2(U2, U2), R3d = pack2(U3, U3);

        // h_{t+1} = acc + sum_r (-2 a_s m_r) R_r   (Nsum part already in kA)
        accA = fma2(m2a[0], R0d, accA); accB = fma2(m2b[0], R0d, accB);
        accA = fma2(m2a[1], R1d, accA); accB = fma2(m2b[1], R1d, accB);
        accA = fma2(m2a[2], R2d, accA); accB = fma2(m2b[2], R2d, accB);
        accA = fma2(m2a[3], R3d, accA); accB = fma2(m2b[3], R3d, accB);
        hA = accA; hB = accB;

        // ---- outputs ----
        if (wid == 0 && lane == 0) {
            u64 u01 = fma2(neg2, R01, NS01);   // u_true = Nsum - 2R
            u64 u23 = fma2(neg2, R23, NS23);
            S01 = fma2(c9, S01, u01);
            S23 = fma2(c9, S23, u23);
            u64 o01 = mul2(asd, S01);
            u64 o23 = mul2(asd, S23);
            float o0, o1, o2, o3;
            unpack2(o01, o0, o1); unpack2(o23, o2, o3);
            *(float4*)(outb + (size_t)t * 20) = make_float4(o0, o1, o2, o3);
        } else if (wid == 1 && lane < INPN) {
            X = fmaf(0.9f, X, xv);
            outb[(size_t)t * 20 + 4 + lane] = 0.1f * X;
            xv = xn;
            xn = xf;
        }
    }
}

extern "C" void kernel_launch(void* const* d_in, const int* in_sizes, int n_in,
                              void* d_out, int out_size) {
    const float* x = (const float*)d_in[0];
    const float* m = (const float*)d_in[1];
    const float* n = (const float*)d_in[2];
    const float* I = (const float*)d_in[3];
    rnn_kernel<<<BATCH, NTHR>>>(x, m, n, I, (float*)d_out);
}